// round 2
// baseline (speedup 1.0000x reference)
#include <cuda_runtime.h>
#include <cuda_bf16.h>

#define MAXN 50176
#define MAXE 850176

// -------- scratch (device globals; no allocation allowed) --------
__device__ float  g_xl[MAXN * 64];      // lin(x)  [N,64]
__device__ float  g_si[MAXN];           // per-node dst-side logit
__device__ float  g_sj[MAXN];           // per-node src-side logit
__device__ int    g_deg[MAXN];          // in-degree (incl. self loop)
__device__ int    g_rowptr[MAXN + 1];
__device__ int    g_cursor[MAXN];
__device__ int    g_csrc[MAXE + MAXN];  // CSR src ids (dst-sorted)
__device__ double g_bnsum[128];         // [0:64) sum, [64:128) sumsq

// -------- K1: xl = x @ W^T, per-node attention scalars, + init duties --------
__global__ void k_gemm(const float* __restrict__ x, const float* __restrict__ W,
                       const float* __restrict__ emb,
                       const float* __restrict__ att_i, const float* __restrict__ att_j,
                       const float* __restrict__ att_em_i, const float* __restrict__ att_em_j,
                       int N) {
    __shared__ float2 Wt2[64][32];      // Wt2[k][l] = (W[2l][k], W[2l+1][k])
    int tid = threadIdx.x;
    if (blockIdx.x == 0 && tid < 128) g_bnsum[tid] = 0.0;   // fused init
    for (int s = tid; s < 64 * 32; s += 256) {
        int k = s >> 5, l = s & 31;
        Wt2[k][l] = make_float2(W[(2 * l) * 64 + k], W[(2 * l + 1) * 64 + k]);
    }
    __syncthreads();
    int warp = tid >> 5, lane = tid & 31;
    int c0 = 2 * lane;
    float ai0 = att_i[c0],    ai1 = att_i[c0 + 1];
    float aj0 = att_j[c0],    aj1 = att_j[c0 + 1];
    float e0i = att_em_i[c0], e1i = att_em_i[c0 + 1];
    float e0j = att_em_j[c0], e1j = att_em_j[c0 + 1];

    for (int r = blockIdx.x * 8 + warp; r < N; r += gridDim.x * 8) {
        float xv0 = x[r * 64 + lane];
        float xv1 = x[r * 64 + 32 + lane];
        float a0 = 0.f, a1 = 0.f;
#pragma unroll
        for (int k = 0; k < 32; k++) {
            float xk = __shfl_sync(0xffffffffu, xv0, k);
            float2 w = Wt2[k][lane];
            a0 = fmaf(xk, w.x, a0);
            a1 = fmaf(xk, w.y, a1);
        }
#pragma unroll
        for (int k = 0; k < 32; k++) {
            float xk = __shfl_sync(0xffffffffu, xv1, k);
            float2 w = Wt2[32 + k][lane];
            a0 = fmaf(xk, w.x, a0);
            a1 = fmaf(xk, w.y, a1);
        }
        *(float2*)&g_xl[r * 64 + c0] = make_float2(a0, a1);

        float2 em = *(const float2*)&emb[r * 64 + c0];
        float si = a0 * ai0 + a1 * ai1 + em.x * e0i + em.y * e1i;
        float sj = a0 * aj0 + a1 * aj1 + em.x * e0j + em.y * e1j;
#pragma unroll
        for (int o = 16; o; o >>= 1) {
            si += __shfl_xor_sync(0xffffffffu, si, o);
            sj += __shfl_xor_sync(0xffffffffu, sj, o);
        }
        if (lane == 0) { g_si[r] = si; g_sj[r] = sj; g_deg[r] = 1; }  // fused deg init
    }
}

// -------- K2: in-degree count --------
__global__ void k_count(const int* __restrict__ ei, int E) {
    int e = blockIdx.x * blockDim.x + threadIdx.x;
    if (e < E) atomicAdd(&g_deg[ei[E + e]], 1);
}

// -------- K3: exclusive scan — single block, smem-staged, 4 barriers total --------
__global__ void k_scan(int N) {
    extern __shared__ int sdeg[];                 // N ints (~200 KB)
    __shared__ int wtot[32];
    __shared__ int s_total;
    int tid = threadIdx.x, lane = tid & 31, wid = tid >> 5;

    // phase 1: coalesced bulk load
    for (int i = tid; i < N; i += 1024) sdeg[i] = g_deg[i];
    __syncthreads();

    // phase 2: per-thread chunk sum (chunk=49 → odd stride, conflict-free)
    int chunk = (N + 1023) >> 10;
    int beg = tid * chunk;
    int end = beg + chunk; if (end > N) end = N;
    int sum = 0;
    for (int i = beg; i < end; i++) sum += sdeg[i];

    // block exclusive scan over 1024 per-thread sums
    int incl = sum;
#pragma unroll
    for (int d = 1; d < 32; d <<= 1) {
        int t = __shfl_up_sync(0xffffffffu, incl, d);
        if (lane >= d) incl += t;
    }
    if (lane == 31) wtot[wid] = incl;
    __syncthreads();
    if (wid == 0) {
        int s = wtot[lane];
        int si_ = s;
#pragma unroll
        for (int d = 1; d < 32; d <<= 1) {
            int t = __shfl_up_sync(0xffffffffu, si_, d);
            if (lane >= d) si_ += t;
        }
        wtot[lane] = si_ - s;
        if (lane == 31) s_total = si_;
    }
    __syncthreads();
    int excl = wtot[wid] + incl - sum;

    // phase 3: in-place chunk prefix in smem
    for (int i = beg; i < end; i++) { int v = sdeg[i]; sdeg[i] = excl; excl += v; }
    __syncthreads();

    // phase 4: coalesced write-out
    for (int i = tid; i < N; i += 1024) {
        int p = sdeg[i];
        g_rowptr[i] = p;
        g_cursor[i] = p;
    }
    if (tid == 0) g_rowptr[N] = s_total;
}

// -------- K4: scatter edges (+ self loops) into CSR --------
__global__ void k_scatter(const int* __restrict__ ei, int E, int N) {
    int idx = blockIdx.x * blockDim.x + threadIdx.x;
    if (idx < E) {
        int s = ei[idx], d = ei[E + idx];
        int p = atomicAdd(&g_cursor[d], 1);
        g_csrc[p] = s;
    } else if (idx < E + N) {
        int n = idx - E;
        int p = atomicAdd(&g_cursor[n], 1);
        g_csrc[p] = n;
    }
}

// -------- K5: per-node ONLINE softmax + weighted gather (one warp / node) --------
__global__ void k_agg(const float* __restrict__ bias, float* __restrict__ out, int N) {
    int gwarp = (blockIdx.x * blockDim.x + threadIdx.x) >> 5;
    int lane = threadIdx.x & 31;
    if (gwarp >= N) return;
    int i = gwarp;
    int beg = g_rowptr[i], end = g_rowptr[i + 1];
    float si = g_si[i];
    int c0 = 2 * lane;

    float m = -1e30f, ssum = 0.f, ax = 0.f, ay = 0.f;
    for (int k = beg; k < end; ++k) {
        int s = g_csrc[k];                          // warp-uniform broadcast load
        float a = si + g_sj[s];
        a = a >= 0.f ? a : 0.2f * a;
        float mnew = fmaxf(m, a);
        float c = __expf(m - mnew);                 // 1 if no new max; 0 on first iter
        float w = __expf(a - mnew);
        float2 v = *(const float2*)&g_xl[s * 64 + c0];
        ssum = fmaf(ssum, c, w);
        ax = fmaf(ax, c, w * v.x);
        ay = fmaf(ay, c, w * v.y);
        m = mnew;
    }
    float inv = 1.f / (ssum + 1e-16f);
    float2 b2 = *(const float2*)&bias[c0];
    *(float2*)&out[i * 64 + c0] = make_float2(fmaf(ax, inv, b2.x), fmaf(ay, inv, b2.y));
}

// -------- K6: BN stats (double partials) --------
__global__ void k_bnred(const float* __restrict__ out, int N) {
    __shared__ double ssum[256], ssq[256];
    int tid = threadIdx.x;
    double s = 0.0, q = 0.0;
    int total = N * 64;
    for (int idx = blockIdx.x * 256 + tid; idx < total; idx += gridDim.x * 256) {
        double v = (double)out[idx];
        s += v; q += v * v;
    }
    ssum[tid] = s; ssq[tid] = q;
    __syncthreads();
    if (tid < 128) { ssum[tid] += ssum[tid + 128]; ssq[tid] += ssq[tid + 128]; }
    __syncthreads();
    if (tid < 64) {
        double S = ssum[tid] + ssum[tid + 64];
        double Q = ssq[tid] + ssq[tid + 64];
        atomicAdd(&g_bnsum[tid], S);
        atomicAdd(&g_bnsum[64 + tid], Q);
    }
}

// -------- K7: apply BN + ReLU (finalize fused per-block) --------
__global__ void k_bnapply(const float* __restrict__ gamma, const float* __restrict__ beta,
                          float* __restrict__ out, int N) {
    __shared__ float s_scale[64], s_shift[64];
    int tid = threadIdx.x;
    if (tid < 64) {
        double mu  = g_bnsum[tid] / (double)N;
        double var = g_bnsum[64 + tid] / (double)N - mu * mu;
        float sc = (float)(rsqrt(var + 1e-5)) * gamma[tid];
        s_scale[tid] = sc;
        s_shift[tid] = fmaf(-(float)mu, sc, beta[tid]);
    }
    __syncthreads();
    int idx = blockIdx.x * blockDim.x + tid;
    if (idx >= N * 64) return;
    int c = idx & 63;
    float v = fmaf(out[idx], s_scale[c], s_shift[c]);
    out[idx] = fmaxf(v, 0.f);
}

extern "C" void kernel_launch(void* const* d_in, const int* in_sizes, int n_in,
                              void* d_out, int out_size) {
    const float* x        = (const float*)d_in[0];
    const int*   ei       = (const int*)d_in[1];
    const float* emb      = (const float*)d_in[2];
    const float* W        = (const float*)d_in[3];
    const float* att_i    = (const float*)d_in[4];
    const float* att_j    = (const float*)d_in[5];
    const float* att_em_i = (const float*)d_in[6];
    const float* att_em_j = (const float*)d_in[7];
    const float* bias     = (const float*)d_in[8];
    const float* gamma    = (const float*)d_in[9];
    const float* beta     = (const float*)d_in[10];
    float* out = (float*)d_out;

    int N = in_sizes[0] / 64;
    int E = in_sizes[1] / 2;

    static bool attr_set = false;
    if (!attr_set) {
        cudaFuncSetAttribute(k_scan, cudaFuncAttributeMaxDynamicSharedMemorySize, MAXN * 4);
        attr_set = true;
    }
    size_t scan_smem = (size_t)N * 4;

    k_gemm<<<1480, 256>>>(x, W, emb, att_i, att_j, att_em_i, att_em_j, N);
    k_count<<<(E + 255) / 256, 256>>>(ei, E);
    k_scan<<<1, 1024, scan_smem>>>(N);
    k_scatter<<<(E + N + 255) / 256, 256>>>(ei, E, N);
    k_agg<<<(N + 7) / 8, 256>>>(bias, out, N);
    k_bnred<<<1184, 256>>>(out, N);
    k_bnapply<<<(N * 64 + 255) / 256, 256>>>(gamma, beta, out, N);
}

// round 3
// speedup vs baseline: 1.0316x; 1.0316x over previous
#include <cuda_runtime.h>
#include <cuda_bf16.h>

#define MAXN 50176
#define MAXE 850176

// -------- scratch (device globals; no allocation allowed) --------
__device__ float  g_xl[MAXN * 64];      // lin(x)  [N,64]
__device__ float  g_si[MAXN];           // per-node dst-side logit
__device__ float  g_sj[MAXN];           // per-node src-side logit
__device__ int    g_deg[MAXN];          // in-degree (incl. self loop)
__device__ int    g_rowptr[MAXN + 1];
__device__ int    g_cursor[MAXN];
__device__ int    g_csrc[MAXE + MAXN];  // CSR src ids (dst-sorted)
__device__ double g_bnsum[128];         // [0:64) sum, [64:128) sumsq

// -------- K1: xl = x @ W^T, per-node attention scalars, + init duties --------
__global__ void k_gemm(const float* __restrict__ x, const float* __restrict__ W,
                       const float* __restrict__ emb,
                       const float* __restrict__ att_i, const float* __restrict__ att_j,
                       const float* __restrict__ att_em_i, const float* __restrict__ att_em_j,
                       int N) {
    __shared__ float2 Wt2[64][32];      // Wt2[k][l] = (W[2l][k], W[2l+1][k])
    int tid = threadIdx.x;
    if (blockIdx.x == 0 && tid < 128) g_bnsum[tid] = 0.0;   // fused init
    for (int s = tid; s < 64 * 32; s += 256) {
        int k = s >> 5, l = s & 31;
        Wt2[k][l] = make_float2(W[(2 * l) * 64 + k], W[(2 * l + 1) * 64 + k]);
    }
    __syncthreads();
    int warp = tid >> 5, lane = tid & 31;
    int c0 = 2 * lane;
    float ai0 = att_i[c0],    ai1 = att_i[c0 + 1];
    float aj0 = att_j[c0],    aj1 = att_j[c0 + 1];
    float e0i = att_em_i[c0], e1i = att_em_i[c0 + 1];
    float e0j = att_em_j[c0], e1j = att_em_j[c0 + 1];

    for (int r = blockIdx.x * 8 + warp; r < N; r += gridDim.x * 8) {
        float xv0 = x[r * 64 + lane];
        float xv1 = x[r * 64 + 32 + lane];
        float a0 = 0.f, a1 = 0.f;
#pragma unroll
        for (int k = 0; k < 32; k++) {
            float xk = __shfl_sync(0xffffffffu, xv0, k);
            float2 w = Wt2[k][lane];
            a0 = fmaf(xk, w.x, a0);
            a1 = fmaf(xk, w.y, a1);
        }
#pragma unroll
        for (int k = 0; k < 32; k++) {
            float xk = __shfl_sync(0xffffffffu, xv1, k);
            float2 w = Wt2[32 + k][lane];
            a0 = fmaf(xk, w.x, a0);
            a1 = fmaf(xk, w.y, a1);
        }
        *(float2*)&g_xl[r * 64 + c0] = make_float2(a0, a1);

        float2 em = *(const float2*)&emb[r * 64 + c0];
        float si = a0 * ai0 + a1 * ai1 + em.x * e0i + em.y * e1i;
        float sj = a0 * aj0 + a1 * aj1 + em.x * e0j + em.y * e1j;
#pragma unroll
        for (int o = 16; o; o >>= 1) {
            si += __shfl_xor_sync(0xffffffffu, si, o);
            sj += __shfl_xor_sync(0xffffffffu, sj, o);
        }
        if (lane == 0) { g_si[r] = si; g_sj[r] = sj; g_deg[r] = 1; }  // fused deg init
    }
}

// -------- K2: in-degree count (4 edges/thread, vectorized) --------
__global__ void k_count(const int* __restrict__ ei, int E) {
    int t = blockIdx.x * blockDim.x + threadIdx.x;
    int E4 = E >> 2;
    if (t < E4) {
        int4 d4 = *(const int4*)&ei[E + 4 * t];
        atomicAdd(&g_deg[d4.x], 1);
        atomicAdd(&g_deg[d4.y], 1);
        atomicAdd(&g_deg[d4.z], 1);
        atomicAdd(&g_deg[d4.w], 1);
    } else {
        int e = 4 * E4 + (t - E4);                  // scalar tail (E % 4 edges)
        if (e < E) atomicAdd(&g_deg[ei[E + e]], 1);
    }
}

// -------- K3: exclusive scan — single block, smem-staged --------
__global__ void k_scan(int N) {
    extern __shared__ int sdeg[];                 // N ints (~200 KB)
    __shared__ int wtot[32];
    __shared__ int s_total;
    int tid = threadIdx.x, lane = tid & 31, wid = tid >> 5;

    for (int i = tid; i < N; i += 1024) sdeg[i] = g_deg[i];
    __syncthreads();

    int chunk = (N + 1023) >> 10;
    int beg = tid * chunk;
    int end = beg + chunk; if (end > N) end = N;
    int sum = 0;
    for (int i = beg; i < end; i++) sum += sdeg[i];

    int incl = sum;
#pragma unroll
    for (int d = 1; d < 32; d <<= 1) {
        int t = __shfl_up_sync(0xffffffffu, incl, d);
        if (lane >= d) incl += t;
    }
    if (lane == 31) wtot[wid] = incl;
    __syncthreads();
    if (wid == 0) {
        int s = wtot[lane];
        int si_ = s;
#pragma unroll
        for (int d = 1; d < 32; d <<= 1) {
            int t = __shfl_up_sync(0xffffffffu, si_, d);
            if (lane >= d) si_ += t;
        }
        wtot[lane] = si_ - s;
        if (lane == 31) s_total = si_;
    }
    __syncthreads();
    int excl = wtot[wid] + incl - sum;

    for (int i = beg; i < end; i++) { int v = sdeg[i]; sdeg[i] = excl; excl += v; }
    __syncthreads();

    for (int i = tid; i < N; i += 1024) {
        int p = sdeg[i];
        g_rowptr[i] = p;
        g_cursor[i] = p;
    }
    if (tid == 0) g_rowptr[N] = s_total;
}

// -------- K4: scatter edges (+ self loops) into CSR (4 edges/thread) --------
__global__ void k_scatter(const int* __restrict__ ei, int E, int N) {
    int t = blockIdx.x * blockDim.x + threadIdx.x;
    int E4 = E >> 2;
    if (t < E4) {
        int4 s4 = *(const int4*)&ei[4 * t];
        int4 d4 = *(const int4*)&ei[E + 4 * t];
        int p0 = atomicAdd(&g_cursor[d4.x], 1);
        int p1 = atomicAdd(&g_cursor[d4.y], 1);
        int p2 = atomicAdd(&g_cursor[d4.z], 1);
        int p3 = atomicAdd(&g_cursor[d4.w], 1);
        g_csrc[p0] = s4.x;
        g_csrc[p1] = s4.y;
        g_csrc[p2] = s4.z;
        g_csrc[p3] = s4.w;
    } else {
        int r = t - E4;
        int tail = E - 4 * E4;
        if (r < tail) {                              // scalar edge tail
            int e = 4 * E4 + r;
            int p = atomicAdd(&g_cursor[ei[E + e]], 1);
            g_csrc[p] = ei[e];
        } else if (r - tail < N) {                   // self loops
            int n = r - tail;
            int p = atomicAdd(&g_cursor[n], 1);
            g_csrc[p] = n;
        }
    }
}

// -------- K5: single-pass softmax agg, NO max shift (logits are O(10)) --------
__global__ void k_agg(const float* __restrict__ bias, float* __restrict__ out, int N) {
    int gwarp = (blockIdx.x * blockDim.x + threadIdx.x) >> 5;
    int lane = threadIdx.x & 31;
    if (gwarp >= N) return;
    int i = gwarp;
    int beg = g_rowptr[i], end = g_rowptr[i + 1];
    float si = g_si[i];
    int c0 = 2 * lane;

    float ssum = 0.f, ax = 0.f, ay = 0.f;
    for (int k = beg; k < end; ++k) {
        int s = g_csrc[k];                          // warp-uniform broadcast load
        float a = si + g_sj[s];
        a = a >= 0.f ? a : 0.2f * a;
        float w = __expf(a);                        // independent per-edge; no chain
        float2 v = *(const float2*)&g_xl[s * 64 + c0];
        ssum += w;
        ax = fmaf(w, v.x, ax);
        ay = fmaf(w, v.y, ay);
    }
    float inv = 1.f / (ssum + 1e-16f);
    float2 b2 = *(const float2*)&bias[c0];
    *(float2*)&out[i * 64 + c0] = make_float2(fmaf(ax, inv, b2.x), fmaf(ay, inv, b2.y));
}

// -------- K6: BN stats (double partials) --------
__global__ void k_bnred(const float* __restrict__ out, int N) {
    __shared__ double ssum[256], ssq[256];
    int tid = threadIdx.x;
    double s = 0.0, q = 0.0;
    int total = N * 64;
    for (int idx = blockIdx.x * 256 + tid; idx < total; idx += gridDim.x * 256) {
        double v = (double)out[idx];
        s += v; q += v * v;
    }
    ssum[tid] = s; ssq[tid] = q;
    __syncthreads();
    if (tid < 128) { ssum[tid] += ssum[tid + 128]; ssq[tid] += ssq[tid + 128]; }
    __syncthreads();
    if (tid < 64) {
        double S = ssum[tid] + ssum[tid + 64];
        double Q = ssq[tid] + ssq[tid + 64];
        atomicAdd(&g_bnsum[tid], S);
        atomicAdd(&g_bnsum[64 + tid], Q);
    }
}

// -------- K7: apply BN + ReLU (finalize fused per-block) --------
__global__ void k_bnapply(const float* __restrict__ gamma, const float* __restrict__ beta,
                          float* __restrict__ out, int N) {
    __shared__ float s_scale[64], s_shift[64];
    int tid = threadIdx.x;
    if (tid < 64) {
        double mu  = g_bnsum[tid] / (double)N;
        double var = g_bnsum[64 + tid] / (double)N - mu * mu;
        float sc = (float)(rsqrt(var + 1e-5)) * gamma[tid];
        s_scale[tid] = sc;
        s_shift[tid] = fmaf(-(float)mu, sc, beta[tid]);
    }
    __syncthreads();
    int idx = blockIdx.x * blockDim.x + tid;
    if (idx >= N * 64) return;
    int c = idx & 63;
    float v = fmaf(out[idx], s_scale[c], s_shift[c]);
    out[idx] = fmaxf(v, 0.f);
}

extern "C" void kernel_launch(void* const* d_in, const int* in_sizes, int n_in,
                              void* d_out, int out_size) {
    const float* x        = (const float*)d_in[0];
    const int*   ei       = (const int*)d_in[1];
    const float* emb      = (const float*)d_in[2];
    const float* W        = (const float*)d_in[3];
    const float* att_i    = (const float*)d_in[4];
    const float* att_j    = (const float*)d_in[5];
    const float* att_em_i = (const float*)d_in[6];
    const float* att_em_j = (const float*)d_in[7];
    const float* bias     = (const float*)d_in[8];
    const float* gamma    = (const float*)d_in[9];
    const float* beta     = (const float*)d_in[10];
    float* out = (float*)d_out;

    int N = in_sizes[0] / 64;
    int E = in_sizes[1] / 2;

    cudaFuncSetAttribute(k_scan, cudaFuncAttributeMaxDynamicSharedMemorySize, MAXN * 4);
    size_t scan_smem = (size_t)N * 4;

    int E4 = E >> 2;
    int cnt_threads = E4 + (E - 4 * E4);            // vector part + scalar tail
    int sct_threads = cnt_threads + N;              // + self loops

    k_gemm<<<1480, 256>>>(x, W, emb, att_i, att_j, att_em_i, att_em_j, N);
    k_count<<<(cnt_threads + 255) / 256, 256>>>(ei, E);
    k_scan<<<1, 1024, scan_smem>>>(N);
    k_scatter<<<(sct_threads + 255) / 256, 256>>>(ei, E, N);
    k_agg<<<(N + 7) / 8, 256>>>(bias, out, N);
    k_bnred<<<1184, 256>>>(out, N);
    k_bnapply<<<(N * 64 + 255) / 256, 256>>>(gamma, beta, out, N);
}